// round 10
// baseline (speedup 1.0000x reference)
#include <cuda_runtime.h>
#include <cstdint>

// dcn_56925496541545: 3x (sparse 9x9 neighbor-mean stencil -> convex combo -> sigmoid),
// output = x[:,0]. Inputs: d_in[0] = x [N,9] f32, d_in[1] = w1 [1] f32. Out: [N] f32.
//
// R9: R8 (pipelined cp.async + tanh-space algebra) with IPT=3 -> 27.6 KB smem
//     -> 8 blocks/SM = 64 resident warps (was 6 blocks / ~44 warps).
//     __launch_bounds__(256,8) pins regs <= 32 so the reg file fits exactly.

#define THREADS 256
#define IPT 3
#define PPB (THREADS * IPT)               // patches per block = 768
#define F4_PER_CHUNK ((THREADS * 9) / 4)  // 576 float4 per 256-patch chunk

__device__ __forceinline__ float tanh_fast(float t) {
    float th;
    asm("tanh.approx.f32 %0, %1;" : "=f"(th) : "f"(t));
    return th;
}

// 3-iteration evaluation in tanh-space (post-sigmoid affine folded into the
// next iteration's weights; exact). DCE: iter2 keeps {0,1,3,4}, iter3 {0}.
__device__ __forceinline__ float patch_eval(const float* __restrict__ a,
                                            float h1, float h3, float h5, float h8,
                                            float g1, float g3, float g5, float g8) {
    const float a0 = a[0], a1 = a[1], a2 = a[2],
                a3 = a[3], a4 = a[4], a5 = a[5],
                a6 = a[6], a7 = a[7], a8 = a[8];

    // ---- iteration 1 (a-space -> u-space), all 9 live ----
    float u0, u1, u2, u3, u4, u5, u6, u7, u8;
    {
        const float p14 = a1 + a4, p34 = a3 + a4, p45 = a4 + a5, p47 = a4 + a7;
        const float q02 = a0 + a2, q06 = a0 + a6, q28 = a2 + a8, q68 = a6 + a8;
        const float b00 = p34 + a1;
        const float b02 = p14 + a5;
        const float b20 = p34 + a7;
        const float b22 = p45 + a7;
        const float b01 = (q02 + p34) + a5;
        const float b10 = (q06 + p14) + a7;
        const float b12 = (q28 + p47) + a1;
        const float b21 = (q68 + p45) + a3;
        const float s   = ((b01 + a1) + a7) + q68;   // sum of all 9
        const float b11 = s - a4;

        u0 = tanh_fast(fmaf(h1, a0, h3 * b00));
        u1 = tanh_fast(fmaf(h1, a1, h5 * b01));
        u2 = tanh_fast(fmaf(h1, a2, h3 * b02));
        u3 = tanh_fast(fmaf(h1, a3, h5 * b10));
        u4 = tanh_fast(fmaf(h1, a4, h8 * b11));
        u5 = tanh_fast(fmaf(h1, a5, h5 * b12));
        u6 = tanh_fast(fmaf(h1, a6, h3 * b20));
        u7 = tanh_fast(fmaf(h1, a7, h5 * b21));
        u8 = tanh_fast(fmaf(h1, a8, h3 * b22));
    }

    // ---- iteration 2 (u-space -> v-space), only {0,1,3,4} live ----
    float v0, v1, v3, v4;
    {
        const float p34 = u3 + u4;
        const float b00 = p34 + u1;
        const float b01 = ((u0 + u2) + p34) + u5;
        const float b10 = ((u0 + u6) + (u1 + u4)) + u7;
        const float s   = (((b01 + u1) + u7) + u6) + u8;  // sum of all 9
        const float b11 = s - u4;

        v0 = tanh_fast(fmaf(g1, u0, fmaf(g3, b00, 0.25f)));
        v1 = tanh_fast(fmaf(g1, u1, fmaf(g5, b01, 0.25f)));
        v3 = tanh_fast(fmaf(g1, u3, fmaf(g5, b10, 0.25f)));
        v4 = tanh_fast(fmaf(g1, u4, fmaf(g8, b11, 0.25f)));
    }

    // ---- iteration 3: only element 0; final sigmoid reconstructed ----
    const float b00 = (v1 + v3) + v4;
    const float t   = tanh_fast(fmaf(g1, v0, fmaf(g3, b00, 0.25f)));
    return fmaf(0.5f, t, 0.5f);
}

__global__ __launch_bounds__(THREADS, 8)
void dcn_56925496541545_kernel(const float* __restrict__ x,
                               const float* __restrict__ w1p,
                               float* __restrict__ out,
                               int n)  // number of patches
{
    __shared__ float sx[PPB * 9];  // 27648 B -> 8 blocks/SM

    const long long patch0 = (long long)blockIdx.x * PPB;
    const long long baseF  = patch0 * 9;
    const int tid = threadIdx.x;

    const float w1 = __ldg(w1p);   // issue early; overlaps with cp.async setup
    const bool full = (patch0 + PPB <= (long long)n);

    const uint32_t s_base = (uint32_t)__cvta_generic_to_shared(sx);

    if (full) {
        // ---- issue 3 commit groups, one per 256-patch chunk (9216 B each) ----
        const float4* g = reinterpret_cast<const float4*>(x + baseF);  // 16B aligned
        #pragma unroll
        for (int c = 0; c < IPT; ++c) {
            const int b4 = c * F4_PER_CHUNK;
            {
                int i = b4 + tid;
                asm volatile("cp.async.cg.shared.global [%0], [%1], 16;\n"
                             :: "r"(s_base + i * 16u), "l"(g + i));
            }
            {
                int i = b4 + tid + THREADS;
                asm volatile("cp.async.cg.shared.global [%0], [%1], 16;\n"
                             :: "r"(s_base + i * 16u), "l"(g + i));
            }
            if (tid < F4_PER_CHUNK - 2 * THREADS) {   // 64 threads carry the 3rd float4
                int i = b4 + tid + 2 * THREADS;
                asm volatile("cp.async.cg.shared.global [%0], [%1], 16;\n"
                             :: "r"(s_base + i * 16u), "l"(g + i));
            }
            asm volatile("cp.async.commit_group;\n" ::: "memory");
        }
    } else {
        // tail block: guarded scalar loads, single barrier, guarded compute below
        const long long totalF = (long long)n * 9;
        for (int i = tid; i < PPB * 9; i += THREADS) {
            long long gidx = baseF + i;
            sx[i] = (gidx < totalF) ? x[gidx] : 0.0f;
        }
    }

    const float w2 = 1.0f - w1;
    // iter1 weights (0.5 and 1/len folded)
    const float h1 = 0.5f * w1;
    const float h3 = 0.5f * w2 * (1.0f / 3.0f);
    const float h5 = 0.5f * w2 * (1.0f / 5.0f);
    const float h8 = 0.5f * w2 * (1.0f / 8.0f);
    // tanh-space weights for iters 2,3: g1 = w1/4, g_len = w2/(4*len)
    const float g1 = 0.25f * w1;
    const float g3 = 0.25f * w2 * (1.0f / 3.0f);
    const float g5 = 0.25f * w2 * (1.0f / 5.0f);
    const float g8 = 0.25f * w2 * (1.0f / 8.0f);

    if (full) {
        // ---- pipelined consume: chunk c computes while chunks c+1.. are in flight ----
        #define CONSUME_CHUNK(C, WAITN)                                              \
            {                                                                        \
                asm volatile("cp.async.wait_group %0;\n" :: "n"(WAITN) : "memory");  \
                __syncthreads();                                                     \
                const int lp = tid + (C) * THREADS;                                  \
                out[patch0 + lp] = patch_eval(&sx[lp * 9],                           \
                                              h1, h3, h5, h8, g1, g3, g5, g8);       \
            }
        CONSUME_CHUNK(0, 2)
        CONSUME_CHUNK(1, 1)
        CONSUME_CHUNK(2, 0)
        #undef CONSUME_CHUNK
    } else {
        __syncthreads();
        #pragma unroll
        for (int c = 0; c < IPT; ++c) {
            const int lp = tid + c * THREADS;
            const long long p = patch0 + lp;
            if (p < (long long)n)
                out[p] = patch_eval(&sx[lp * 9], h1, h3, h5, h8, g1, g3, g5, g8);
        }
    }
}

extern "C" void kernel_launch(void* const* d_in, const int* in_sizes, int n_in,
                              void* d_out, int out_size) {
    const float* x   = (const float*)d_in[0];
    const float* w1  = (const float*)d_in[1];
    float* out       = (float*)d_out;
    const int n      = in_sizes[0] / 9;  // number of patches

    const int blocks = (int)(((long long)n + PPB - 1) / PPB);
    dcn_56925496541545_kernel<<<blocks, THREADS>>>(x, w1, out, n);
}